// round 1
// baseline (speedup 1.0000x reference)
#include <cuda_runtime.h>

// Problem constants
#define NTOK 64
#define HEADS 8
#define HD 32
#define DIM 256

// Bias scratch: [H][N][N]
__device__ float g_bias[HEADS * NTOK * NTOK];

// ---- packed f32x2 helpers (Blackwell-only FFMA2 via PTX) ----
__device__ __forceinline__ unsigned long long ffma2(unsigned long long a,
                                                    unsigned long long b,
                                                    unsigned long long c) {
    unsigned long long d;
    asm("fma.rn.f32x2 %0, %1, %2, %3;" : "=l"(d) : "l"(a), "l"(b), "l"(c));
    return d;
}
__device__ __forceinline__ unsigned long long dup2(float p) {
    unsigned long long r;
    asm("mov.b64 %0, {%1, %1};" : "=l"(r) : "f"(p));
    return r;
}
__device__ __forceinline__ float2 u2f2(unsigned long long v) {
    float2 r;
    asm("mov.b64 {%0, %1}, %2;" : "=f"(r.x), "=f"(r.y) : "l"(v));
    return r;
}

// ---------------------------------------------------------------------------
// Kernel 1: relative-position bias MLP  ->  g_bias[h][n][m]
// rel_pos: [N,N,2], w1: [2,256], b1:[256], w2:[256,8], b2:[8]
// ---------------------------------------------------------------------------
__global__ void bias_kernel(const float* __restrict__ rel_pos,
                            const float* __restrict__ w1,
                            const float* __restrict__ b1,
                            const float* __restrict__ w2,
                            const float* __restrict__ b2) {
    int nm = blockIdx.x * blockDim.x + threadIdx.x;  // 0..4095
    if (nm >= NTOK * NTOK) return;
    float r0 = rel_pos[nm * 2 + 0];
    float r1 = rel_pos[nm * 2 + 1];
    float acc[HEADS];
#pragma unroll
    for (int h = 0; h < HEADS; h++) acc[h] = 0.f;
    for (int k = 0; k < 256; k++) {
        float hk = fmaf(r0, __ldg(&w1[k]), fmaf(r1, __ldg(&w1[256 + k]), __ldg(&b1[k])));
        hk = fmaxf(hk, 0.f);
#pragma unroll
        for (int h = 0; h < HEADS; h++)
            acc[h] = fmaf(hk, __ldg(&w2[k * HEADS + h]), acc[h]);
    }
#pragma unroll
    for (int h = 0; h < HEADS; h++)
        g_bias[h * (NTOK * NTOK) + nm] = acc[h] + __ldg(&b2[h]);
}

// ---------------------------------------------------------------------------
// Kernel 2: attention. One CTA = (batch, head, branch). 256 threads.
// ---------------------------------------------------------------------------
__global__ __launch_bounds__(256)
void attn_kernel(const float* __restrict__ qkv,
                 const float* __restrict__ ass_qkv,
                 float* __restrict__ out, int B) {
    // padded / swizzled smem (see bank analysis in commit message)
    __shared__ float2 qs[NTOK * 17];   // q row stride 17 f2 (pad)
    __shared__ float2 ks[NTOK * 16];   // k, XOR-swizzled within row
    __shared__ float2 vs[NTOK * 16];   // v, plain
    __shared__ float  Ss[NTOK * 65];   // scores / probs, stride 65
    __shared__ float  rowinv[NTOK];

    const int b = blockIdx.y;
    const int h = blockIdx.x >> 1;
    const int branch = blockIdx.x & 1;
    const float* src = branch ? ass_qkv : qkv;
    float* dst = out + (size_t)branch * B * NTOK * DIM;
    const int t = threadIdx.x;

    const float scale = 0.17677669529663687f;  // 32^-0.5 (folded into q)
    const float* base = src + (size_t)b * (NTOK * 3 * DIM) + h * HD;

    // ---- load q,k,v (each 64x32 fp32) ----
#pragma unroll
    for (int i = t; i < 512; i += 256) {
        int row = i >> 3, f4 = i & 7;
        const float* rb = base + row * (3 * DIM) + f4 * 4;
        float4 qv = *(const float4*)(rb);
        float4 kv = *(const float4*)(rb + DIM);
        float4 vv = *(const float4*)(rb + 2 * DIM);
        int dp = f4 * 2;
        qs[row * 17 + dp    ] = make_float2(qv.x * scale, qv.y * scale);
        qs[row * 17 + dp + 1] = make_float2(qv.z * scale, qv.w * scale);
        int sw = (row >> 2) & 15;
        ks[row * 16 + (dp ^ sw)]       = make_float2(kv.x, kv.y);
        ks[row * 16 + ((dp + 1) ^ sw)] = make_float2(kv.z, kv.w);
        vs[row * 16 + dp]     = make_float2(vv.x, vv.y);
        vs[row * 16 + dp + 1] = make_float2(vv.z, vv.w);
    }
    __syncthreads();

    // ---- S = (q*scale) @ k^T : 4x4 tile per thread, f32x2 over head dim ----
    {
        const int rt = t >> 4, ct = t & 15;
        unsigned long long acc[4][4];
#pragma unroll
        for (int i = 0; i < 4; i++)
#pragma unroll
            for (int j = 0; j < 4; j++) acc[i][j] = 0ull;
        const unsigned long long* qp = (const unsigned long long*)(qs) + (4 * rt) * 17;
        const unsigned long long* kp = (const unsigned long long*)(ks) + (4 * ct) * 16;
#pragma unroll
        for (int dp = 0; dp < 16; dp++) {
            unsigned long long qv[4], kv[4];
#pragma unroll
            for (int i = 0; i < 4; i++) qv[i] = qp[i * 17 + dp];
            const int dsw = dp ^ ct;  // undo store swizzle (c>>2 == ct)
#pragma unroll
            for (int j = 0; j < 4; j++) kv[j] = kp[j * 16 + dsw];
#pragma unroll
            for (int i = 0; i < 4; i++)
#pragma unroll
                for (int j = 0; j < 4; j++)
                    acc[i][j] = ffma2(qv[i], kv[j], acc[i][j]);
        }
#pragma unroll
        for (int i = 0; i < 4; i++)
#pragma unroll
            for (int j = 0; j < 4; j++) {
                float2 v = u2f2(acc[i][j]);
                Ss[(4 * rt + i) * 65 + 4 * ct + j] = v.x + v.y;
            }
    }
    __syncthreads();

    // ---- softmax with bias (4 threads per row, 16 cols each) ----
    {
        const int r = t >> 2, seg = t & 3;
        const float* bp = g_bias + h * (NTOK * NTOK) + r * NTOK + seg * 16;
        float* srow = Ss + r * 65 + seg * 16;
        float vals[16];
#pragma unroll
        for (int i4 = 0; i4 < 4; i4++) {
            float4 bb = *(const float4*)(bp + i4 * 4);
            vals[i4 * 4 + 0] = srow[i4 * 4 + 0] + bb.x;
            vals[i4 * 4 + 1] = srow[i4 * 4 + 1] + bb.y;
            vals[i4 * 4 + 2] = srow[i4 * 4 + 2] + bb.z;
            vals[i4 * 4 + 3] = srow[i4 * 4 + 3] + bb.w;
        }
        float mx = vals[0];
#pragma unroll
        for (int i = 1; i < 16; i++) mx = fmaxf(mx, vals[i]);
        mx = fmaxf(mx, __shfl_xor_sync(0xffffffffu, mx, 1));
        mx = fmaxf(mx, __shfl_xor_sync(0xffffffffu, mx, 2));
        float sum = 0.f;
#pragma unroll
        for (int i = 0; i < 16; i++) {
            float e = __expf(vals[i] - mx);
            srow[i] = e;  // unnormalized P; normalize in epilogue
            sum += e;
        }
        sum += __shfl_xor_sync(0xffffffffu, sum, 1);
        sum += __shfl_xor_sync(0xffffffffu, sum, 2);
        if (seg == 0) rowinv[r] = 1.0f / sum;
    }
    __syncthreads();

    // ---- O = P @ V : 2 rows x 4 d per thread (f32x2 over d) ----
    {
        const int rg = t >> 3, dg = t & 7;
        const int r0 = rg * 2, r1 = r0 + 1;
        unsigned long long a00 = 0ull, a01 = 0ull, a10 = 0ull, a11 = 0ull;
        const float* p0r = Ss + r0 * 65;
        const float* p1r = Ss + r1 * 65;
        const unsigned long long* vp = (const unsigned long long*)(vs) + dg * 2;
#pragma unroll 8
        for (int m = 0; m < NTOK; m++) {
            unsigned long long pd0 = dup2(p0r[m]);
            unsigned long long pd1 = dup2(p1r[m]);
            unsigned long long v0 = vp[m * 16];
            unsigned long long v1 = vp[m * 16 + 1];
            a00 = ffma2(pd0, v0, a00);
            a01 = ffma2(pd0, v1, a01);
            a10 = ffma2(pd1, v0, a10);
            a11 = ffma2(pd1, v1, a11);
        }
        const float inv0 = rowinv[r0], inv1 = rowinv[r1];
        float2 o00 = u2f2(a00), o01 = u2f2(a01), o10 = u2f2(a10), o11 = u2f2(a11);
        float* d0 = dst + ((size_t)b * NTOK + r0) * DIM + h * HD + dg * 4;
        float* d1 = dst + ((size_t)b * NTOK + r1) * DIM + h * HD + dg * 4;
        *(float4*)d0 = make_float4(o00.x * inv0, o00.y * inv0, o01.x * inv0, o01.y * inv0);
        *(float4*)d1 = make_float4(o10.x * inv1, o10.y * inv1, o11.x * inv1, o11.y * inv1);
    }
}

// ---------------------------------------------------------------------------
extern "C" void kernel_launch(void* const* d_in, const int* in_sizes, int n_in,
                              void* d_out, int out_size) {
    const float* qkv     = (const float*)d_in[0];
    const float* ass_qkv = (const float*)d_in[1];
    const float* rel_pos = (const float*)d_in[2];
    const float* w1      = (const float*)d_in[3];
    const float* b1      = (const float*)d_in[4];
    const float* w2      = (const float*)d_in[5];
    const float* b2      = (const float*)d_in[6];
    float* out = (float*)d_out;

    const int B = in_sizes[0] / (NTOK * 3 * DIM);  // 2048

    bias_kernel<<<16, 256>>>(rel_pos, w1, b1, w2, b2);
    attn_kernel<<<dim3(HEADS * 2, B), 256>>>(qkv, ass_qkv, out, B);
}

// round 2
// speedup vs baseline: 1.1619x; 1.1619x over previous
#include <cuda_runtime.h>

#define NTOK 64
#define HEADS 8
#define HD 32
#define DIM 256

typedef unsigned long long ull;

// Bias scratch: [H][N][N]
__device__ float g_bias[HEADS * NTOK * NTOK];

// ---- packed f32x2 helpers ----
__device__ __forceinline__ ull ffma2(ull a, ull b, ull c) {
    ull d;
    asm("fma.rn.f32x2 %0, %1, %2, %3;" : "=l"(d) : "l"(a), "l"(b), "l"(c));
    return d;
}
__device__ __forceinline__ ull dup2(float p) {
    ull r;
    asm("mov.b64 %0, {%1, %1};" : "=l"(r) : "f"(p));
    return r;
}
__device__ __forceinline__ float2 u2f2(ull v) {
    float2 r;
    asm("mov.b64 {%0, %1}, %2;" : "=f"(r.x), "=f"(r.y) : "l"(v));
    return r;
}

// ---------------------------------------------------------------------------
// Kernel 1: relative-position bias MLP -> g_bias[h][n][m]
// weights staged in smem, f32x2 inner product over 8 heads.
// ---------------------------------------------------------------------------
__global__ __launch_bounds__(256)
void bias_kernel(const float* __restrict__ rel_pos,
                 const float* __restrict__ w1,
                 const float* __restrict__ b1,
                 const float* __restrict__ w2,
                 const float* __restrict__ b2) {
    __shared__ float w1a[256], w1b[256], b1s[256];
    __shared__ float4 w2s[512];  // [256 k][2 f4] = 2048 floats
    const int t = threadIdx.x;
    w1a[t] = w1[t];
    w1b[t] = w1[256 + t];
    b1s[t] = b1[t];
#pragma unroll
    for (int i = t; i < 512; i += 256)
        w2s[i] = ((const float4*)w2)[i];
    __syncthreads();

    const int nm = blockIdx.x * 256 + t;  // 0..4095
    const float r0 = rel_pos[2 * nm];
    const float r1 = rel_pos[2 * nm + 1];
    ull acc[4] = {0ull, 0ull, 0ull, 0ull};
    const ulonglong2* w2u = (const ulonglong2*)w2s;
#pragma unroll 8
    for (int k = 0; k < 256; k++) {
        float hk = fmaxf(fmaf(r0, w1a[k], fmaf(r1, w1b[k], b1s[k])), 0.f);
        ull hd = dup2(hk);
        ulonglong2 wa = w2u[2 * k];
        ulonglong2 wb = w2u[2 * k + 1];
        acc[0] = ffma2(hd, wa.x, acc[0]);
        acc[1] = ffma2(hd, wa.y, acc[1]);
        acc[2] = ffma2(hd, wb.x, acc[2]);
        acc[3] = ffma2(hd, wb.y, acc[3]);
    }
#pragma unroll
    for (int p = 0; p < 4; p++) {
        float2 v = u2f2(acc[p]);
        g_bias[(2 * p) * (NTOK * NTOK) + nm] = v.x + b2[2 * p];
        g_bias[(2 * p + 1) * (NTOK * NTOK) + nm] = v.y + b2[2 * p + 1];
    }
}

// ---------------------------------------------------------------------------
// Kernel 2: attention. One CTA = (batch, head, branch). 256 threads.
// All smem traffic is LDS.128/STS.128; softmax entirely in registers.
// ---------------------------------------------------------------------------
__global__ __launch_bounds__(256)
void attn_kernel(const float* __restrict__ qkv,
                 const float* __restrict__ ass_qkv,
                 float* __restrict__ out, int B) {
    __shared__ float4 qs4[NTOK * 9];   // q: row stride 9 f4 (pad)
    __shared__ float4 ks4[NTOK * 8];   // k: 16B-granular XOR swizzle
    __shared__ float4 vs4[NTOK * 8];   // v: plain
    __shared__ float4 Ps4[NTOK * 17];  // P: row stride 17 f4 (pad)

    const int b = blockIdx.y;
    const int h = blockIdx.x >> 1;
    const int branch = blockIdx.x & 1;
    const float* src = branch ? ass_qkv : qkv;
    float* dst = out + (size_t)branch * B * NTOK * DIM;
    const int t = threadIdx.x;
    const float scale = 0.17677669529663687f;  // 32^-0.5, folded into q

    // ---- load q,k,v (each 64x32 fp32 = 8 f4 per row) ----
    const float4* src4 = (const float4*)src + (size_t)b * (NTOK * 192) + h * 8;
#pragma unroll
    for (int i = t; i < 512; i += 256) {
        const int row = i >> 3, f4 = i & 7;
        const float4* rb = src4 + row * 192 + f4;
        float4 qv = rb[0];
        float4 kv = rb[64];
        float4 vv = rb[128];
        qv.x *= scale; qv.y *= scale; qv.z *= scale; qv.w *= scale;
        qs4[row * 9 + f4] = qv;
        ks4[row * 8 + (f4 ^ (row >> 3))] = kv;
        vs4[row * 8 + f4] = vv;
    }
    __syncthreads();

    // ---- S = q @ k^T : 4x4 tile per thread (rt = row grp, ct = col grp) ----
    const int rt = t >> 4, ct = t & 15;
    float s[4][4];
    {
        ull acc[4][4];
#pragma unroll
        for (int i = 0; i < 4; i++)
#pragma unroll
            for (int j = 0; j < 4; j++) acc[i][j] = 0ull;

        const ulonglong2* qp = (const ulonglong2*)(qs4 + 4 * rt * 9);
        const ulonglong2* kp = (const ulonglong2*)(ks4 + 4 * ct * 8);
        const int sw = ct >> 1;  // ((4ct+j)>>3) is j-independent
#pragma unroll
        for (int dp4 = 0; dp4 < 8; dp4++) {
            ulonglong2 qv[4], kv[4];
#pragma unroll
            for (int i = 0; i < 4; i++) qv[i] = qp[i * 9 + dp4];
            const int dsw = dp4 ^ sw;
#pragma unroll
            for (int j = 0; j < 4; j++) kv[j] = kp[j * 8 + dsw];
#pragma unroll
            for (int i = 0; i < 4; i++)
#pragma unroll
                for (int j = 0; j < 4; j++) {
                    acc[i][j] = ffma2(qv[i].x, kv[j].x, acc[i][j]);
                    acc[i][j] = ffma2(qv[i].y, kv[j].y, acc[i][j]);
                }
        }
#pragma unroll
        for (int i = 0; i < 4; i++)
#pragma unroll
            for (int j = 0; j < 4; j++) {
                float2 v = u2f2(acc[i][j]);
                s[i][j] = v.x + v.y;
            }
    }

    // ---- bias + softmax fully in registers (rows live in one half-warp) ----
    {
        const float4* bias4 = (const float4*)(g_bias + h * (NTOK * NTOK));
        float mx[4], sm[4];
#pragma unroll
        for (int i = 0; i < 4; i++) {
            float4 bb = bias4[(4 * rt + i) * 16 + ct];
            s[i][0] += bb.x; s[i][1] += bb.y; s[i][2] += bb.z; s[i][3] += bb.w;
            mx[i] = fmaxf(fmaxf(s[i][0], s[i][1]), fmaxf(s[i][2], s[i][3]));
        }
#pragma unroll
        for (int off = 1; off <= 8; off <<= 1) {
#pragma unroll
            for (int i = 0; i < 4; i++)
                mx[i] = fmaxf(mx[i], __shfl_xor_sync(0xffffffffu, mx[i], off));
        }
#pragma unroll
        for (int i = 0; i < 4; i++) {
            s[i][0] = __expf(s[i][0] - mx[i]);
            s[i][1] = __expf(s[i][1] - mx[i]);
            s[i][2] = __expf(s[i][2] - mx[i]);
            s[i][3] = __expf(s[i][3] - mx[i]);
            sm[i] = (s[i][0] + s[i][1]) + (s[i][2] + s[i][3]);
        }
#pragma unroll
        for (int off = 1; off <= 8; off <<= 1) {
#pragma unroll
            for (int i = 0; i < 4; i++)
                sm[i] += __shfl_xor_sync(0xffffffffu, sm[i], off);
        }
#pragma unroll
        for (int i = 0; i < 4; i++) {
            float inv = __fdividef(1.0f, sm[i]);
            Ps4[(4 * rt + i) * 17 + ct] =
                make_float4(s[i][0] * inv, s[i][1] * inv, s[i][2] * inv, s[i][3] * inv);
        }
    }
    __syncthreads();

    // ---- O = P @ V : 2 rows x 1 f4 per thread, 4 m per iteration ----
    {
        const int rg = t >> 3, dg = t & 7;
        ull a00 = 0ull, a01 = 0ull, a10 = 0ull, a11 = 0ull;
        const float4* p0 = Ps4 + (2 * rg) * 17;
        const float4* p1 = Ps4 + (2 * rg + 1) * 17;
        const ulonglong2* vp = (const ulonglong2*)vs4 + dg;
#pragma unroll 4
        for (int m4 = 0; m4 < 16; m4++) {
            float4 pa = p0[m4];
            float4 pb = p1[m4];
            {
                ulonglong2 v = vp[(4 * m4 + 0) * 8];
                ull da = dup2(pa.x), db = dup2(pb.x);
                a00 = ffma2(da, v.x, a00); a01 = ffma2(da, v.y, a01);
                a10 = ffma2(db, v.x, a10); a11 = ffma2(db, v.y, a11);
            }
            {
                ulonglong2 v = vp[(4 * m4 + 1) * 8];
                ull da = dup2(pa.y), db = dup2(pb.y);
                a00 = ffma2(da, v.x, a00); a01 = ffma2(da, v.y, a01);
                a10 = ffma2(db, v.x, a10); a11 = ffma2(db, v.y, a11);
            }
            {
                ulonglong2 v = vp[(4 * m4 + 2) * 8];
                ull da = dup2(pa.z), db = dup2(pb.z);
                a00 = ffma2(da, v.x, a00); a01 = ffma2(da, v.y, a01);
                a10 = ffma2(db, v.x, a10); a11 = ffma2(db, v.y, a11);
            }
            {
                ulonglong2 v = vp[(4 * m4 + 3) * 8];
                ull da = dup2(pa.w), db = dup2(pb.w);
                a00 = ffma2(da, v.x, a00); a01 = ffma2(da, v.y, a01);
                a10 = ffma2(db, v.x, a10); a11 = ffma2(db, v.y, a11);
            }
        }
        float2 o00 = u2f2(a00), o01 = u2f2(a01), o10 = u2f2(a10), o11 = u2f2(a11);
        float* d0 = dst + ((size_t)b * NTOK + 2 * rg) * DIM + h * HD + dg * 4;
        *(float4*)d0 = make_float4(o00.x, o00.y, o01.x, o01.y);
        *(float4*)(d0 + DIM) = make_float4(o10.x, o10.y, o11.x, o11.y);
    }
}

// ---------------------------------------------------------------------------
extern "C" void kernel_launch(void* const* d_in, const int* in_sizes, int n_in,
                              void* d_out, int out_size) {
    const float* qkv     = (const float*)d_in[0];
    const float* ass_qkv = (const float*)d_in[1];
    const float* rel_pos = (const float*)d_in[2];
    const float* w1      = (const float*)d_in[3];
    const float* b1      = (const float*)d_in[4];
    const float* w2      = (const float*)d_in[5];
    const float* b2      = (const float*)d_in[6];
    float* out = (float*)d_out;

    const int B = in_sizes[0] / (NTOK * 3 * DIM);  // 2048

    bias_kernel<<<16, 256>>>(rel_pos, w1, b1, w2, b2);
    attn_kernel<<<dim3(HEADS * 2, B), 256>>>(qkv, ass_qkv, out, B);
}

// round 4
// speedup vs baseline: 1.3273x; 1.1424x over previous
#include <cuda_runtime.h>

#define NTOK 64
#define HEADS 8
#define HD 32
#define DIM 256

typedef unsigned long long ull;

// Bias scratch: [H][N][N]
__device__ float g_bias[HEADS * NTOK * NTOK];

__device__ __forceinline__ ull ffma2(ull a, ull b, ull c) {
    ull d;
    asm("fma.rn.f32x2 %0, %1, %2, %3;" : "=l"(d) : "l"(a), "l"(b), "l"(c));
    return d;
}
__device__ __forceinline__ float2 u2f2(ull v) {
    float2 r;
    asm("mov.b64 {%0, %1}, %2;" : "=f"(r.x), "=f"(r.y) : "l"(v));
    return r;
}
__device__ __forceinline__ ull dup2(float p) {
    ull r;
    asm("mov.b64 %0, {%1, %1};" : "=l"(r) : "f"(p));
    return r;
}

// ---------------------------------------------------------------------------
// Kernel 1: relative-position bias MLP -> g_bias[h][n][m]
// ---------------------------------------------------------------------------
__global__ __launch_bounds__(256)
void bias_kernel(const float* __restrict__ rel_pos,
                 const float* __restrict__ w1,
                 const float* __restrict__ b1,
                 const float* __restrict__ w2,
                 const float* __restrict__ b2) {
    __shared__ float w1a[256], w1b[256], b1s[256];
    __shared__ float4 w2s[512];
    const int t = threadIdx.x;
    w1a[t] = w1[t];
    w1b[t] = w1[256 + t];
    b1s[t] = b1[t];
#pragma unroll
    for (int i = t; i < 512; i += 256)
        w2s[i] = ((const float4*)w2)[i];
    __syncthreads();

    const int nm = blockIdx.x * 256 + t;
    const float r0 = rel_pos[2 * nm];
    const float r1 = rel_pos[2 * nm + 1];
    ull acc[4] = {0ull, 0ull, 0ull, 0ull};
    const ulonglong2* w2u = (const ulonglong2*)w2s;
#pragma unroll 8
    for (int k = 0; k < 256; k++) {
        float hk = fmaxf(fmaf(r0, w1a[k], fmaf(r1, w1b[k], b1s[k])), 0.f);
        ull hd = dup2(hk);
        ulonglong2 wa = w2u[2 * k];
        ulonglong2 wb = w2u[2 * k + 1];
        acc[0] = ffma2(hd, wa.x, acc[0]);
        acc[1] = ffma2(hd, wa.y, acc[1]);
        acc[2] = ffma2(hd, wb.x, acc[2]);
        acc[3] = ffma2(hd, wb.y, acc[3]);
    }
#pragma unroll
    for (int p = 0; p < 4; p++) {
        float2 v = u2f2(acc[p]);
        g_bias[(2 * p) * (NTOK * NTOK) + nm] = v.x + b2[2 * p];
        g_bias[(2 * p + 1) * (NTOK * NTOK) + nm] = v.y + b2[2 * p + 1];
    }
}

// ---------------------------------------------------------------------------
// Kernel 2: attention. One CTA = (batch, head, branch), 64 threads.
// 8x8 S-tiles / 8x4 PV-tiles per thread to halve smem crossbar bytes.
// V stored transposed so PV uses f32x2 packed over m-pairs (no dup movs).
// ---------------------------------------------------------------------------
__global__ __launch_bounds__(64)
void attn_kernel(const float* __restrict__ qkv,
                 const float* __restrict__ ass_qkv,
                 float* __restrict__ out, int B) {
    __shared__ float4 qs4[NTOK * 8];    // [row][slot], slot = f4 ^ (row>>3)
    __shared__ float4 ks4[NTOK * 8];    // same swizzle
    __shared__ float  vT[HD * 68];      // [d][m], row stride 68 floats
    __shared__ float4 Ps4[NTOK * 16];   // [row][slot], slot = m4 ^ (row>>3)

    const int b = blockIdx.y;
    const int h = blockIdx.x >> 1;
    const int branch = blockIdx.x & 1;
    const float* src = branch ? ass_qkv : qkv;
    float* dst = out + (size_t)branch * B * NTOK * DIM;
    const int t = threadIdx.x;
    const float scale = 0.17677669529663687f;  // 32^-0.5 folded into q

    // ---- load q,k,v ----
    const float4* src4 = (const float4*)src + (size_t)b * (NTOK * 192) + h * 8;
#pragma unroll
    for (int it = 0; it < 8; it++) {
        const int i = it * 64 + t;
        const int row = i >> 3, f4 = i & 7;
        const float4* rb = src4 + row * 192 + f4;
        float4 qv = rb[0];
        float4 kv = rb[64];
        float4 vv = rb[128];
        qv.x *= scale; qv.y *= scale; qv.z *= scale; qv.w *= scale;
        const int sw = f4 ^ (row >> 3);
        qs4[row * 8 + sw] = qv;
        ks4[row * 8 + sw] = kv;
        float* vr = vT + (4 * f4) * 68 + row;
        vr[0]      = vv.x;
        vr[68]     = vv.y;
        vr[136]    = vv.z;
        vr[204]    = vv.w;
    }
    __syncthreads();

    // ---- S = q @ k^T : 8x8 tile per thread (rb = t>>3 rows, cb = t&7 cols) ----
    const int rb = t >> 3, cb = t & 7;
    float acc[8][8];
#pragma unroll
    for (int i = 0; i < 8; i++)
#pragma unroll
        for (int j = 0; j < 8; j++) acc[i][j] = 0.f;

#pragma unroll 2
    for (int dp4 = 0; dp4 < 8; dp4++) {
        float4 qv[8];
#pragma unroll
        for (int i = 0; i < 8; i++)
            qv[i] = qs4[(8 * rb + i) * 8 + (dp4 ^ rb)];
#pragma unroll
        for (int j = 0; j < 8; j++) {
            float4 kv = ks4[(8 * cb + j) * 8 + (dp4 ^ cb)];
#pragma unroll
            for (int i = 0; i < 8; i++) {
                acc[i][j] = fmaf(qv[i].x, kv.x,
                            fmaf(qv[i].y, kv.y,
                            fmaf(qv[i].z, kv.z,
                            fmaf(qv[i].w, kv.w, acc[i][j]))));
            }
        }
    }

    // ---- bias + softmax (reduce over 8 cb lanes; rows in registers) ----
    {
        const float4* bias4 = (const float4*)(g_bias + h * (NTOK * NTOK));
        float mx[8], sm[8];
#pragma unroll
        for (int i = 0; i < 8; i++) {
            float4 b0 = bias4[(8 * rb + i) * 16 + 2 * cb];
            float4 b1 = bias4[(8 * rb + i) * 16 + 2 * cb + 1];
            acc[i][0] += b0.x; acc[i][1] += b0.y; acc[i][2] += b0.z; acc[i][3] += b0.w;
            acc[i][4] += b1.x; acc[i][5] += b1.y; acc[i][6] += b1.z; acc[i][7] += b1.w;
            float m0 = fmaxf(fmaxf(acc[i][0], acc[i][1]), fmaxf(acc[i][2], acc[i][3]));
            float m1 = fmaxf(fmaxf(acc[i][4], acc[i][5]), fmaxf(acc[i][6], acc[i][7]));
            mx[i] = fmaxf(m0, m1);
        }
#pragma unroll
        for (int off = 1; off <= 4; off <<= 1)
#pragma unroll
            for (int i = 0; i < 8; i++)
                mx[i] = fmaxf(mx[i], __shfl_xor_sync(0xffffffffu, mx[i], off));
#pragma unroll
        for (int i = 0; i < 8; i++) {
            float s0 = 0.f;
#pragma unroll
            for (int j = 0; j < 8; j++) {
                acc[i][j] = __expf(acc[i][j] - mx[i]);
                s0 += acc[i][j];
            }
            sm[i] = s0;
        }
#pragma unroll
        for (int off = 1; off <= 4; off <<= 1)
#pragma unroll
            for (int i = 0; i < 8; i++)
                sm[i] += __shfl_xor_sync(0xffffffffu, sm[i], off);
#pragma unroll
        for (int i = 0; i < 8; i++) {
            const float inv = __fdividef(1.0f, sm[i]);
            const int rowbase = (8 * rb + i) * 16;
            Ps4[rowbase + ((2 * cb) ^ rb)] =
                make_float4(acc[i][0] * inv, acc[i][1] * inv, acc[i][2] * inv, acc[i][3] * inv);
            Ps4[rowbase + ((2 * cb + 1) ^ rb)] =
                make_float4(acc[i][4] * inv, acc[i][5] * inv, acc[i][6] * inv, acc[i][7] * inv);
        }
    }
    __syncthreads();

    // ---- O = P @ V : 8 rows x 4 d per thread, f32x2 packed over m-pairs ----
    {
        const int rb2 = t >> 3, db = t & 7;  // rows 8*rb2.., d = 4*db..
        ull o[8][4];
#pragma unroll
        for (int i = 0; i < 8; i++)
#pragma unroll
            for (int d = 0; d < 4; d++) o[i][d] = 0ull;

#pragma unroll 2
        for (int m4 = 0; m4 < 16; m4++) {
            ulonglong2 p[8];
#pragma unroll
            for (int i = 0; i < 8; i++)
                p[i] = *(const ulonglong2*)&Ps4[(8 * rb2 + i) * 16 + (m4 ^ rb2)];
#pragma unroll
            for (int d = 0; d < 4; d++) {
                ulonglong2 vv = *(const ulonglong2*)(vT + (4 * db + d) * 68 + 4 * m4);
#pragma unroll
                for (int i = 0; i < 8; i++) {
                    o[i][d] = ffma2(p[i].x, vv.x, o[i][d]);
                    o[i][d] = ffma2(p[i].y, vv.y, o[i][d]);
                }
            }
        }
        float* dbase = dst + ((size_t)b * NTOK + 8 * rb2) * DIM + h * HD + 4 * db;
#pragma unroll
        for (int i = 0; i < 8; i++) {
            float2 f0 = u2f2(o[i][0]);
            float2 f1 = u2f2(o[i][1]);
            float2 f2 = u2f2(o[i][2]);
            float2 f3 = u2f2(o[i][3]);
            *(float4*)(dbase + i * DIM) =
                make_float4(f0.x + f0.y, f1.x + f1.y, f2.x + f2.y, f3.x + f3.y);
        }
    }
}

// ---------------------------------------------------------------------------
extern "C" void kernel_launch(void* const* d_in, const int* in_sizes, int n_in,
                              void* d_out, int out_size) {
    const float* qkv     = (const float*)d_in[0];
    const float* ass_qkv = (const float*)d_in[1];
    const float* rel_pos = (const float*)d_in[2];
    const float* w1      = (const float*)d_in[3];
    const float* b1      = (const float*)d_in[4];
    const float* w2      = (const float*)d_in[5];
    const float* b2      = (const float*)d_in[6];
    float* out = (float*)d_out;

    const int B = in_sizes[0] / (NTOK * 3 * DIM);  // 2048

    bias_kernel<<<16, 256>>>(rel_pos, w1, b1, w2, b2);
    attn_kernel<<<dim3(HEADS * 2, B), 64>>>(qkv, ass_qkv, out, B);
}

// round 6
// speedup vs baseline: 2.0077x; 1.5126x over previous
#include <cuda_runtime.h>
#include <cstdint>

#define NTOK 64
#define HEADS 8
#define HD 32
#define DIM 256

typedef unsigned long long ull;

__device__ float g_bias[HEADS * NTOK * NTOK];

// ---------------- packed helpers ----------------
__device__ __forceinline__ ull ffma2(ull a, ull b, ull c) {
    ull d; asm("fma.rn.f32x2 %0, %1, %2, %3;" : "=l"(d) : "l"(a), "l"(b), "l"(c)); return d;
}
__device__ __forceinline__ ull dup2(float p) {
    ull r; asm("mov.b64 %0, {%1, %1};" : "=l"(r) : "f"(p)); return r;
}
__device__ __forceinline__ float2 u2f2(ull v) {
    float2 r; asm("mov.b64 {%0, %1}, %2;" : "=f"(r.x), "=f"(r.y) : "l"(v)); return r;
}
__device__ __forceinline__ uint16_t f2bf(float x) {
    uint16_t r; asm("cvt.rn.bf16.f32 %0, %1;" : "=h"(r) : "f"(x)); return r;
}
__device__ __forceinline__ float bf2f(uint16_t h) {
    return __uint_as_float(((uint32_t)h) << 16);
}
// split pair (a0 low half, a1 high half) into bf16 hi + residual lo words
__device__ __forceinline__ void split2(float a0, float a1, uint32_t& hi, uint32_t& lo) {
    uint16_t h0 = f2bf(a0), h1 = f2bf(a1);
    uint16_t l0 = f2bf(a0 - bf2f(h0)), l1 = f2bf(a1 - bf2f(h1));
    hi = (uint32_t)h0 | ((uint32_t)h1 << 16);
    lo = (uint32_t)l0 | ((uint32_t)l1 << 16);
}
__device__ __forceinline__ uint32_t smem_u32(const void* p) {
    uint32_t a;
    asm("{ .reg .u64 t; cvta.to.shared.u64 t, %1; cvt.u32.u64 %0, t; }" : "=r"(a) : "l"(p));
    return a;
}

// ---------------- warp-mma primitives (baseline ISA) ----------------
__device__ __forceinline__ void ldsm4(uint32_t r[4], uint32_t a) {
    asm volatile("ldmatrix.sync.aligned.m8n8.x4.shared.b16 {%0,%1,%2,%3}, [%4];"
        : "=r"(r[0]), "=r"(r[1]), "=r"(r[2]), "=r"(r[3]) : "r"(a));
}
__device__ __forceinline__ void ldsm4t(uint32_t r[4], uint32_t a) {
    asm volatile("ldmatrix.sync.aligned.m8n8.x4.trans.shared.b16 {%0,%1,%2,%3}, [%4];"
        : "=r"(r[0]), "=r"(r[1]), "=r"(r[2]), "=r"(r[3]) : "r"(a));
}
__device__ __forceinline__ void mma16816(float* c, const uint32_t* a, uint32_t b0, uint32_t b1) {
    asm volatile("mma.sync.aligned.m16n8k16.row.col.f32.bf16.bf16.f32 "
        "{%0,%1,%2,%3}, {%4,%5,%6,%7}, {%8,%9}, {%0,%1,%2,%3};"
        : "+f"(c[0]), "+f"(c[1]), "+f"(c[2]), "+f"(c[3])
        : "r"(a[0]), "r"(a[1]), "r"(a[2]), "r"(a[3]), "r"(b0), "r"(b1));
}

// smem tile geometry: [64 rows][40 bf16] = 80B rows; data chunks 0..3 (16B each),
// stored at chunk' = chunk ^ ((row>>3)&3)  -> conflict-free STS + LDSM.
#define BR_STRIDE 30720   // 6 arrays x 5120B per branch
#define MAT_STRIDE 10240  // hi array per matrix (q/k/v), lo at +5120
#define LO_OFF 5120
#define BIAS_OFF 61440    // f32 [64][68]
#define SMEM_TOTAL (61440 + 64 * 68 * 4)

__device__ __forceinline__ uint32_t faddr(uint32_t base, int rowbase, int c0, int lane) {
    int row = rowbase + (lane & 15);
    int chunk = (c0 + (lane >> 4)) ^ ((row >> 3) & 3);
    return base + row * 80 + chunk * 16;
}

// ---------------------------------------------------------------------------
// Kernel 1: relative-position bias MLP -> g_bias[h][n][m]
// ---------------------------------------------------------------------------
__global__ __launch_bounds__(256)
void bias_kernel(const float* __restrict__ rel_pos,
                 const float* __restrict__ w1,
                 const float* __restrict__ b1,
                 const float* __restrict__ w2,
                 const float* __restrict__ b2) {
    __shared__ float w1a[256], w1b[256], b1s[256];
    __shared__ float4 w2s[512];
    const int t = threadIdx.x;
    w1a[t] = w1[t];
    w1b[t] = w1[256 + t];
    b1s[t] = b1[t];
#pragma unroll
    for (int i = t; i < 512; i += 256)
        w2s[i] = ((const float4*)w2)[i];
    __syncthreads();

    const int nm = blockIdx.x * 256 + t;
    const float r0 = rel_pos[2 * nm];
    const float r1 = rel_pos[2 * nm + 1];
    ull acc[4] = {0ull, 0ull, 0ull, 0ull};
    const ulonglong2* w2u = (const ulonglong2*)w2s;
#pragma unroll 8
    for (int k = 0; k < 256; k++) {
        float hk = fmaxf(fmaf(r0, w1a[k], fmaf(r1, w1b[k], b1s[k])), 0.f);
        ull hd = dup2(hk);
        ulonglong2 wa = w2u[2 * k];
        ulonglong2 wb = w2u[2 * k + 1];
        acc[0] = ffma2(hd, wa.x, acc[0]);
        acc[1] = ffma2(hd, wa.y, acc[1]);
        acc[2] = ffma2(hd, wb.x, acc[2]);
        acc[3] = ffma2(hd, wb.y, acc[3]);
    }
#pragma unroll
    for (int p = 0; p < 4; p++) {
        float2 v = u2f2(acc[p]);
        g_bias[(2 * p) * (NTOK * NTOK) + nm] = v.x + b2[2 * p];
        g_bias[(2 * p + 1) * (NTOK * NTOK) + nm] = v.y + b2[2 * p + 1];
    }
}

// ---------------------------------------------------------------------------
// Kernel 2: warp-mma attention. CTA=(b,h), 4 warps; warp = (branch, m-half).
// bf16 hi/lo split, 3 products per GEMM -> fp32-grade accuracy on HMMA.
// ---------------------------------------------------------------------------
__global__ __launch_bounds__(128)
void attn_kernel(const float* __restrict__ qkv,
                 const float* __restrict__ ass_qkv,
                 float* __restrict__ out, int B) {
    extern __shared__ char sm[];
    const int b = blockIdx.y, h = blockIdx.x, t = threadIdx.x;
    const int lane = t & 31, w = t >> 5;
    const float scale = 0.17677669529663687f;

    // ---- cooperative gmem -> smem (split bf16 hi/lo, swizzled) ----
    {
        const float* srcs[2] = {qkv, ass_qkv};
#pragma unroll
        for (int it = 0; it < 24; it++) {
            const int idx = it * 128 + t;          // 0..3071
            const int brl = idx >= 1536;
            const int j = idx - brl * 1536;
            const int mat = j >> 9, tok = (j >> 3) & 63, f = j & 7;
            const float* p = srcs[brl] + (size_t)b * (NTOK * 3 * DIM) + tok * (3 * DIM) + mat * DIM + h * HD + f * 4;
            float4 v = *(const float4*)p;
            if (mat == 0) { v.x *= scale; v.y *= scale; v.z *= scale; v.w *= scale; }
            uint32_t h01, l01, h23, l23;
            split2(v.x, v.y, h01, l01);
            split2(v.z, v.w, h23, l23);
            char* base = sm + brl * BR_STRIDE + mat * MAT_STRIDE;
            const int off = tok * 80 + 16 * ((f >> 1) ^ ((tok >> 3) & 3)) + 8 * (f & 1);
            *(uint2*)(base + off) = make_uint2(h01, h23);
            *(uint2*)(base + LO_OFF + off) = make_uint2(l01, l23);
        }
        // bias -> smem [64][68] f32
        const float4* gb = (const float4*)(g_bias + h * (NTOK * NTOK));
#pragma unroll
        for (int it = 0; it < 8; it++) {
            const int idx = it * 128 + t;
            const int row = idx >> 4, c4 = idx & 15;
            *(float4*)(sm + BIAS_OFF + (row * 68 + c4 * 4) * 4) = gb[idx];
        }
    }
    __syncthreads();

    const int br = w >> 1;           // branch
    const int mb = (w & 1) * 32;     // m-half base row
    const uint32_t sbase = smem_u32(sm) + br * BR_STRIDE;
    const uint32_t qh = sbase, ql = sbase + LO_OFF;
    const uint32_t kh = sbase + MAT_STRIDE, kl = kh + LO_OFF;
    const uint32_t vh = sbase + 2 * MAT_STRIDE, vl = vh + LO_OFF;

    // ---- S = q @ k^T : 2 m16-tiles x 8 n8-tiles, 3 split products ----
    float sacc[2][8][4];
#pragma unroll
    for (int mt = 0; mt < 2; mt++)
#pragma unroll
        for (int nt = 0; nt < 8; nt++)
#pragma unroll
            for (int c = 0; c < 4; c++) sacc[mt][nt][c] = 0.f;

#pragma unroll
    for (int ks = 0; ks < 2; ks++) {
        uint32_t a_h[2][4], a_l[2][4];
        ldsm4(a_h[0], faddr(qh, mb, 2 * ks, lane));
        ldsm4(a_h[1], faddr(qh, mb + 16, 2 * ks, lane));
        ldsm4(a_l[0], faddr(ql, mb, 2 * ks, lane));
        ldsm4(a_l[1], faddr(ql, mb + 16, 2 * ks, lane));
#pragma unroll
        for (int g = 0; g < 4; g++) {
            uint32_t bh[4], bl[4];
            ldsm4(bh, faddr(kh, 16 * g, 2 * ks, lane));
            ldsm4(bl, faddr(kl, 16 * g, 2 * ks, lane));
            // hh
            mma16816(sacc[0][2 * g], a_h[0], bh[0], bh[2]);
            mma16816(sacc[0][2 * g + 1], a_h[0], bh[1], bh[3]);
            mma16816(sacc[1][2 * g], a_h[1], bh[0], bh[2]);
            mma16816(sacc[1][2 * g + 1], a_h[1], bh[1], bh[3]);
            // hl
            mma16816(sacc[0][2 * g], a_h[0], bl[0], bl[2]);
            mma16816(sacc[0][2 * g + 1], a_h[0], bl[1], bl[3]);
            mma16816(sacc[1][2 * g], a_h[1], bl[0], bl[2]);
            mma16816(sacc[1][2 * g + 1], a_h[1], bl[1], bl[3]);
            // lh
            mma16816(sacc[0][2 * g], a_l[0], bh[0], bh[2]);
            mma16816(sacc[0][2 * g + 1], a_l[0], bh[1], bh[3]);
            mma16816(sacc[1][2 * g], a_l[1], bh[0], bh[2]);
            mma16816(sacc[1][2 * g + 1], a_l[1], bh[1], bh[3]);
        }
    }

    // ---- bias + softmax in registers (rows l/4, l/4+8 per m16 tile) ----
    const int r0 = lane >> 2, c2 = (lane & 3) * 2;
    float inva[2], invb[2];
#pragma unroll
    for (int mt = 0; mt < 2; mt++) {
        const int rowA = mb + 16 * mt + r0;
        float mxa = -1e30f, mxb = -1e30f;
#pragma unroll
        for (int nt = 0; nt < 8; nt++) {
            float2 ba = *(const float2*)(sm + BIAS_OFF + (rowA * 68 + nt * 8 + c2) * 4);
            float2 bb = *(const float2*)(sm + BIAS_OFF + ((rowA + 8) * 68 + nt * 8 + c2) * 4);
            sacc[mt][nt][0] += ba.x; sacc[mt][nt][1] += ba.y;
            sacc[mt][nt][2] += bb.x; sacc[mt][nt][3] += bb.y;
            mxa = fmaxf(mxa, fmaxf(sacc[mt][nt][0], sacc[mt][nt][1]));
            mxb = fmaxf(mxb, fmaxf(sacc[mt][nt][2], sacc[mt][nt][3]));
        }
        mxa = fmaxf(mxa, __shfl_xor_sync(0xffffffffu, mxa, 1));
        mxa = fmaxf(mxa, __shfl_xor_sync(0xffffffffu, mxa, 2));
        mxb = fmaxf(mxb, __shfl_xor_sync(0xffffffffu, mxb, 1));
        mxb = fmaxf(mxb, __shfl_xor_sync(0xffffffffu, mxb, 2));
        float sa = 0.f, sb = 0.f;
#pragma unroll
        for (int nt = 0; nt < 8; nt++) {
            sacc[mt][nt][0] = __expf(sacc[mt][nt][0] - mxa);
            sacc[mt][nt][1] = __expf(sacc[mt][nt][1] - mxa);
            sacc[mt][nt][2] = __expf(sacc[mt][nt][2] - mxb);
            sacc[mt][nt][3] = __expf(sacc[mt][nt][3] - mxb);
            sa += sacc[mt][nt][0] + sacc[mt][nt][1];
            sb += sacc[mt][nt][2] + sacc[mt][nt][3];
        }
        sa += __shfl_xor_sync(0xffffffffu, sa, 1);
        sa += __shfl_xor_sync(0xffffffffu, sa, 2);
        sb += __shfl_xor_sync(0xffffffffu, sb, 1);
        sb += __shfl_xor_sync(0xffffffffu, sb, 2);
        inva[mt] = __fdividef(1.0f, sa);
        invb[mt] = __fdividef(1.0f, sb);
    }

    // ---- O = P @ V : P fragments straight from registers, V via ldsm.trans ----
    float oacc[2][4][4];
#pragma unroll
    for (int mt = 0; mt < 2; mt++)
#pragma unroll
        for (int dt = 0; dt < 4; dt++)
#pragma unroll
            for (int c = 0; c < 4; c++) oacc[mt][dt][c] = 0.f;

#pragma unroll
    for (int kk = 0; kk < 4; kk++) {
        uint32_t ph[2][4], pl[2][4];
#pragma unroll
        for (int mt = 0; mt < 2; mt++) {
            split2(sacc[mt][2 * kk][0], sacc[mt][2 * kk][1], ph[mt][0], pl[mt][0]);
            split2(sacc[mt][2 * kk][2], sacc[mt][2 * kk][3], ph[mt][1], pl[mt][1]);
            split2(sacc[mt][2 * kk + 1][0], sacc[mt][2 * kk + 1][1], ph[mt][2], pl[mt][2]);
            split2(sacc[mt][2 * kk + 1][2], sacc[mt][2 * kk + 1][3], ph[mt][3], pl[mt][3]);
        }
#pragma unroll
        for (int dg = 0; dg < 2; dg++) {
            uint32_t vh4[4], vl4[4];
            ldsm4t(vh4, faddr(vh, 16 * kk, 2 * dg, lane));
            ldsm4t(vl4, faddr(vl, 16 * kk, 2 * dg, lane));
            // ph x vh
            mma16816(oacc[0][2 * dg], ph[0], vh4[0], vh4[1]);
            mma16816(oacc[0][2 * dg + 1], ph[0], vh4[2], vh4[3]);
            mma16816(oacc[1][2 * dg], ph[1], vh4[0], vh4[1]);
            mma16816(oacc[1][2 * dg + 1], ph[1], vh4[2], vh4[3]);
            // ph x vl
            mma16816(oacc[0][2 * dg], ph[0], vl4[0], vl4[1]);
            mma16816(oacc[0][2 * dg + 1], ph[0], vl4[2], vl4[3]);
            mma16816(oacc[1][2 * dg], ph[1], vl4[0], vl4[1]);
            mma16816(oacc[1][2 * dg + 1], ph[1], vl4[2], vl4[3]);
            // pl x vh
            mma16816(oacc[0][2 * dg], pl[0], vh4[0], vh4[1]);
            mma16816(oacc[0][2 * dg + 1], pl[0], vh4[2], vh4[3]);
            mma16816(oacc[1][2 * dg], pl[1], vh4[0], vh4[1]);
            mma16816(oacc[1][2 * dg + 1], pl[1], vh4[2], vh4[3]);
        }
    }

    // ---- normalize + store ----
    float* ob = out + (size_t)br * B * NTOK * DIM + (size_t)b * NTOK * DIM + h * HD;
#pragma unroll
    for (int mt = 0; mt < 2; mt++) {
        const int rowA = mb + 16 * mt + r0;
#pragma unroll
        for (int dt = 0; dt < 4; dt++) {
            const int d = dt * 8 + c2;
            *(float2*)(ob + rowA * DIM + d) =
                make_float2(oacc[mt][dt][0] * inva[mt], oacc[mt][dt][1] * inva[mt]);
            *(float2*)(ob + (rowA + 8) * DIM + d) =
                make_float2(oacc[mt][dt][2] * invb[mt], oacc[mt][dt][3] * invb[mt]);
        }
    }
}

// ---------------------------------------------------------------------------
extern "C" void kernel_launch(void* const* d_in, const int* in_sizes, int n_in,
                              void* d_out, int out_size) {
    const float* qkv     = (const float*)d_in[0];
    const float* ass_qkv = (const float*)d_in[1];
    const float* rel_pos = (const float*)d_in[2];
    const float* w1      = (const float*)d_in[3];
    const float* b1      = (const float*)d_in[4];
    const float* w2      = (const float*)d_in[5];
    const float* b2      = (const float*)d_in[6];
    float* out = (float*)d_out;

    const int B = in_sizes[0] / (NTOK * 3 * DIM);  // 2048

    cudaFuncSetAttribute(attn_kernel, cudaFuncAttributeMaxDynamicSharedMemorySize, SMEM_TOTAL);

    bias_kernel<<<16, 256>>>(rel_pos, w1, b1, w2, b2);
    attn_kernel<<<dim3(HEADS, B), 128, SMEM_TOTAL>>>(qkv, ass_qkv, out, B);
}

// round 7
// speedup vs baseline: 2.3366x; 1.1638x over previous
#include <cuda_runtime.h>
#include <cstdint>

#define NTOK 64
#define HEADS 8
#define HD 32
#define DIM 256

typedef unsigned long long ull;

__device__ float g_bias[HEADS * NTOK * NTOK];

// ---------------- packed helpers ----------------
__device__ __forceinline__ ull ffma2(ull a, ull b, ull c) {
    ull d; asm("fma.rn.f32x2 %0, %1, %2, %3;" : "=l"(d) : "l"(a), "l"(b), "l"(c)); return d;
}
__device__ __forceinline__ ull dup2(float p) {
    ull r; asm("mov.b64 %0, {%1, %1};" : "=l"(r) : "f"(p)); return r;
}
__device__ __forceinline__ float2 u2f2(ull v) {
    float2 r; asm("mov.b64 {%0, %1}, %2;" : "=f"(r.x), "=f"(r.y) : "l"(v)); return r;
}
__device__ __forceinline__ uint16_t f2bf(float x) {
    uint16_t r; asm("cvt.rn.bf16.f32 %0, %1;" : "=h"(r) : "f"(x)); return r;
}
__device__ __forceinline__ float bf2f(uint16_t h) {
    return __uint_as_float(((uint32_t)h) << 16);
}
__device__ __forceinline__ void split2(float a0, float a1, uint32_t& hi, uint32_t& lo) {
    uint16_t h0 = f2bf(a0), h1 = f2bf(a1);
    uint16_t l0 = f2bf(a0 - bf2f(h0)), l1 = f2bf(a1 - bf2f(h1));
    hi = (uint32_t)h0 | ((uint32_t)h1 << 16);
    lo = (uint32_t)l0 | ((uint32_t)l1 << 16);
}
__device__ __forceinline__ uint32_t smem_u32(const void* p) {
    uint32_t a;
    asm("{ .reg .u64 t; cvta.to.shared.u64 t, %1; cvt.u32.u64 %0, t; }" : "=r"(a) : "l"(p));
    return a;
}

// ---------------- warp-mma primitives (baseline ISA) ----------------
__device__ __forceinline__ void ldsm4(uint32_t r[4], uint32_t a) {
    asm volatile("ldmatrix.sync.aligned.m8n8.x4.shared.b16 {%0,%1,%2,%3}, [%4];"
        : "=r"(r[0]), "=r"(r[1]), "=r"(r[2]), "=r"(r[3]) : "r"(a));
}
__device__ __forceinline__ void ldsm4t(uint32_t r[4], uint32_t a) {
    asm volatile("ldmatrix.sync.aligned.m8n8.x4.trans.shared.b16 {%0,%1,%2,%3}, [%4];"
        : "=r"(r[0]), "=r"(r[1]), "=r"(r[2]), "=r"(r[3]) : "r"(a));
}
__device__ __forceinline__ void mma16816(float* c, const uint32_t* a, uint32_t b0, uint32_t b1) {
    asm volatile("mma.sync.aligned.m16n8k16.row.col.f32.bf16.bf16.f32 "
        "{%0,%1,%2,%3}, {%4,%5,%6,%7}, {%8,%9}, {%0,%1,%2,%3};"
        : "+f"(c[0]), "+f"(c[1]), "+f"(c[2]), "+f"(c[3])
        : "r"(a[0]), "r"(a[1]), "r"(a[2]), "r"(a[3]), "r"(b0), "r"(b1));
}

// smem tile geometry: [64 rows][40 bf16] = 80B rows; chunks 0..3 (16B),
// stored at chunk' = chunk ^ ((row>>3)&3) -> conflict-free STS + LDSM.
#define BR_STRIDE 30720
#define MAT_STRIDE 10240
#define LO_OFF 5120
#define SMEM_TOTAL 61440

__device__ __forceinline__ uint32_t faddr(uint32_t base, int rowbase, int c0, int lane) {
    int row = rowbase + (lane & 15);
    int chunk = (c0 + (lane >> 4)) ^ ((row >> 3) & 3);
    return base + row * 80 + chunk * 16;
}

// ---------------------------------------------------------------------------
// Kernel 1: relative-position bias MLP -> g_bias[h][n][m]
// ---------------------------------------------------------------------------
__global__ __launch_bounds__(256)
void bias_kernel(const float* __restrict__ rel_pos,
                 const float* __restrict__ w1,
                 const float* __restrict__ b1,
                 const float* __restrict__ w2,
                 const float* __restrict__ b2) {
    __shared__ float w1a[256], w1b[256], b1s[256];
    __shared__ float4 w2s[512];
    const int t = threadIdx.x;
    w1a[t] = w1[t];
    w1b[t] = w1[256 + t];
    b1s[t] = b1[t];
#pragma unroll
    for (int i = t; i < 512; i += 256)
        w2s[i] = ((const float4*)w2)[i];
    __syncthreads();

    const int nm = blockIdx.x * 256 + t;
    const float r0 = rel_pos[2 * nm];
    const float r1 = rel_pos[2 * nm + 1];
    ull acc[4] = {0ull, 0ull, 0ull, 0ull};
    const ulonglong2* w2u = (const ulonglong2*)w2s;
#pragma unroll 8
    for (int k = 0; k < 256; k++) {
        float hk = fmaxf(fmaf(r0, w1a[k], fmaf(r1, w1b[k], b1s[k])), 0.f);
        ull hd = dup2(hk);
        ulonglong2 wa = w2u[2 * k];
        ulonglong2 wb = w2u[2 * k + 1];
        acc[0] = ffma2(hd, wa.x, acc[0]);
        acc[1] = ffma2(hd, wa.y, acc[1]);
        acc[2] = ffma2(hd, wb.x, acc[2]);
        acc[3] = ffma2(hd, wb.y, acc[3]);
    }
#pragma unroll
    for (int p = 0; p < 4; p++) {
        float2 v = u2f2(acc[p]);
        g_bias[(2 * p) * (NTOK * NTOK) + nm] = v.x + b2[2 * p];
        g_bias[(2 * p + 1) * (NTOK * NTOK) + nm] = v.y + b2[2 * p + 1];
    }
}

// ---------------------------------------------------------------------------
// Kernel 2: warp-mma attention. CTA=(b,h), 8 warps; warp = (branch, m-quarter).
// bf16 hi/lo split (3 products) on HMMA; bias straight from L2.
// ---------------------------------------------------------------------------
__global__ __launch_bounds__(256, 2)
void attn_kernel(const float* __restrict__ qkv,
                 const float* __restrict__ ass_qkv,
                 float* __restrict__ out, int B) {
    extern __shared__ char sm[];
    const int b = blockIdx.y, h = blockIdx.x, t = threadIdx.x;
    const int lane = t & 31, w = t >> 5;
    const float scale = 0.17677669529663687f;

    // ---- cooperative gmem -> smem (split bf16 hi/lo, swizzled) ----
    {
        const int brl = t >> 7;              // branch handled by this thread
        const int tid = t & 127;
        const float* srcb = (brl ? ass_qkv : qkv) + (size_t)b * (NTOK * 3 * DIM) + h * HD;
        char* bb = sm + brl * BR_STRIDE;
        const int f = tid & 7;
        const int tokbase = tid >> 3;        // 0..15
#pragma unroll
        for (int it = 0; it < 12; it++) {
            const int mat = it >> 2;
            const int tok = (it & 3) * 16 + tokbase;
            const float4 v0 = *(const float4*)(srcb + tok * (3 * DIM) + mat * DIM + f * 4);
            float4 v = v0;
            if (mat == 0) { v.x *= scale; v.y *= scale; v.z *= scale; v.w *= scale; }
            uint32_t h01, l01, h23, l23;
            split2(v.x, v.y, h01, l01);
            split2(v.z, v.w, h23, l23);
            char* base = bb + mat * MAT_STRIDE;
            const int off = tok * 80 + 16 * ((f >> 1) ^ ((tok >> 3) & 3)) + 8 * (f & 1);
            *(uint2*)(base + off) = make_uint2(h01, h23);
            *(uint2*)(base + LO_OFF + off) = make_uint2(l01, l23);
        }
    }
    __syncthreads();

    const int br = w >> 2;           // branch
    const int mb = (w & 3) * 16;     // m-quarter base row
    const uint32_t sbase = smem_u32(sm) + br * BR_STRIDE;
    const uint32_t qh = sbase, ql = sbase + LO_OFF;
    const uint32_t kh = sbase + MAT_STRIDE, kl = kh + LO_OFF;
    const uint32_t vh = sbase + 2 * MAT_STRIDE, vl = vh + LO_OFF;

    // ---- S = q @ k^T : 1 m16-tile x 8 n8-tiles, 3 split products ----
    float sacc[8][4];
#pragma unroll
    for (int nt = 0; nt < 8; nt++)
#pragma unroll
        for (int c = 0; c < 4; c++) sacc[nt][c] = 0.f;

#pragma unroll
    for (int ks = 0; ks < 2; ks++) {
        uint32_t a_h[4], a_l[4];
        ldsm4(a_h, faddr(qh, mb, 2 * ks, lane));
        ldsm4(a_l, faddr(ql, mb, 2 * ks, lane));
#pragma unroll
        for (int g = 0; g < 4; g++) {
            uint32_t bh[4], bl[4];
            ldsm4(bh, faddr(kh, 16 * g, 2 * ks, lane));
            ldsm4(bl, faddr(kl, 16 * g, 2 * ks, lane));
            mma16816(sacc[2 * g], a_h, bh[0], bh[2]);
            mma16816(sacc[2 * g + 1], a_h, bh[1], bh[3]);
            mma16816(sacc[2 * g], a_h, bl[0], bl[2]);
            mma16816(sacc[2 * g + 1], a_h, bl[1], bl[3]);
            mma16816(sacc[2 * g], a_l, bh[0], bh[2]);
            mma16816(sacc[2 * g + 1], a_l, bh[1], bh[3]);
        }
    }

    // ---- bias (from L2) + softmax in registers ----
    const int r0 = lane >> 2, c2 = (lane & 3) * 2;
    float inva, invb;
    {
        const int rowA = mb + r0;
        const float* bp = g_bias + h * (NTOK * NTOK);
        float mxa = -1e30f, mxb = -1e30f;
#pragma unroll
        for (int nt = 0; nt < 8; nt++) {
            float2 ba = __ldg((const float2*)(bp + rowA * NTOK + nt * 8 + c2));
            float2 bbv = __ldg((const float2*)(bp + (rowA + 8) * NTOK + nt * 8 + c2));
            sacc[nt][0] += ba.x; sacc[nt][1] += ba.y;
            sacc[nt][2] += bbv.x; sacc[nt][3] += bbv.y;
            mxa = fmaxf(mxa, fmaxf(sacc[nt][0], sacc[nt][1]));
            mxb = fmaxf(mxb, fmaxf(sacc[nt][2], sacc[nt][3]));
        }
        mxa = fmaxf(mxa, __shfl_xor_sync(0xffffffffu, mxa, 1));
        mxa = fmaxf(mxa, __shfl_xor_sync(0xffffffffu, mxa, 2));
        mxb = fmaxf(mxb, __shfl_xor_sync(0xffffffffu, mxb, 1));
        mxb = fmaxf(mxb, __shfl_xor_sync(0xffffffffu, mxb, 2));
        float sa = 0.f, sb = 0.f;
#pragma unroll
        for (int nt = 0; nt < 8; nt++) {
            sacc[nt][0] = __expf(sacc[nt][0] - mxa);
            sacc[nt][1] = __expf(sacc[nt][1] - mxa);
            sacc[nt][2] = __expf(sacc[nt][2] - mxb);
            sacc[nt][3] = __expf(sacc[nt][3] - mxb);
            sa += sacc[nt][0] + sacc[nt][1];
            sb += sacc[nt][2] + sacc[nt][3];
        }
        sa += __shfl_xor_sync(0xffffffffu, sa, 1);
        sa += __shfl_xor_sync(0xffffffffu, sa, 2);
        sb += __shfl_xor_sync(0xffffffffu, sb, 1);
        sb += __shfl_xor_sync(0xffffffffu, sb, 2);
        inva = __fdividef(1.0f, sa);
        invb = __fdividef(1.0f, sb);
    }

    // ---- O = P @ V : P fragments from registers, V via ldsm.trans ----
    float oacc[4][4];
#pragma unroll
    for (int dt = 0; dt < 4; dt++)
#pragma unroll
        for (int c = 0; c < 4; c++) oacc[dt][c] = 0.f;

#pragma unroll
    for (int kk = 0; kk < 4; kk++) {
        uint32_t ph[4], pl[4];
        split2(sacc[2 * kk][0], sacc[2 * kk][1], ph[0], pl[0]);
        split2(sacc[2 * kk][2], sacc[2 * kk][3], ph[1], pl[1]);
        split2(sacc[2 * kk + 1][0], sacc[2 * kk + 1][1], ph[2], pl[2]);
        split2(sacc[2 * kk + 1][2], sacc[2 * kk + 1][3], ph[3], pl[3]);
#pragma unroll
        for (int dg = 0; dg < 2; dg++) {
            uint32_t vh4[4], vl4[4];
            ldsm4t(vh4, faddr(vh, 16 * kk, 2 * dg, lane));
            ldsm4t(vl4, faddr(vl, 16 * kk, 2 * dg, lane));
            mma16816(oacc[2 * dg], ph, vh4[0], vh4[1]);
            mma16816(oacc[2 * dg + 1], ph, vh4[2], vh4[3]);
            mma16816(oacc[2 * dg], ph, vl4[0], vl4[1]);
            mma16816(oacc[2 * dg + 1], ph, vl4[2], vl4[3]);
            mma16816(oacc[2 * dg], pl, vh4[0], vh4[1]);
            mma16816(oacc[2 * dg + 1], pl, vh4[2], vh4[3]);
        }
    }

    // ---- normalize + store ----
    float* ob = out + (size_t)br * B * NTOK * DIM + (size_t)b * NTOK * DIM + h * HD;
    const int rowA = mb + r0;
#pragma unroll
    for (int dt = 0; dt < 4; dt++) {
        const int d = dt * 8 + c2;
        *(float2*)(ob + rowA * DIM + d) =
            make_float2(oacc[dt][0] * inva, oacc[dt][1] * inva);
        *(float2*)(ob + (rowA + 8) * DIM + d) =
            make_float2(oacc[dt][2] * invb, oacc[dt][3] * invb);
    }
}

// ---------------------------------------------------------------------------
extern "C" void kernel_launch(void* const* d_in, const int* in_sizes, int n_in,
                              void* d_out, int out_size) {
    const float* qkv     = (const float*)d_in[0];
    const float* ass_qkv = (const float*)d_in[1];
    const float* rel_pos = (const float*)d_in[2];
    const float* w1      = (const float*)d_in[3];
    const float* b1      = (const float*)d_in[4];
    const float* w2      = (const float*)d_in[5];
    const float* b2      = (const float*)d_in[6];
    float* out = (float*)d_out;

    const int B = in_sizes[0] / (NTOK * 3 * DIM);  // 2048

    cudaFuncSetAttribute(attn_kernel, cudaFuncAttributeMaxDynamicSharedMemorySize, SMEM_TOTAL);

    bias_kernel<<<16, 256>>>(rel_pos, w1, b1, w2, b2);
    attn_kernel<<<dim3(HEADS, B), 256, SMEM_TOTAL>>>(qkv, ass_qkv, out, B);
}

// round 8
// speedup vs baseline: 2.8975x; 1.2401x over previous
#include <cuda_runtime.h>
#include <cstdint>

#define NTOK 64
#define HEADS 8
#define HD 32
#define DIM 256

typedef unsigned long long ull;

__device__ float g_bias[HEADS * NTOK * NTOK];

// ---------------- packed helpers ----------------
__device__ __forceinline__ ull ffma2(ull a, ull b, ull c) {
    ull d; asm("fma.rn.f32x2 %0, %1, %2, %3;" : "=l"(d) : "l"(a), "l"(b), "l"(c)); return d;
}
__device__ __forceinline__ ull dup2(float p) {
    ull r; asm("mov.b64 %0, {%1, %1};" : "=l"(r) : "f"(p)); return r;
}
__device__ __forceinline__ float2 u2f2(ull v) {
    float2 r; asm("mov.b64 {%0, %1}, %2;" : "=f"(r.x), "=f"(r.y) : "l"(v)); return r;
}
__device__ __forceinline__ uint16_t f2bf(float x) {
    uint16_t r; asm("cvt.rn.bf16.f32 %0, %1;" : "=h"(r) : "f"(x)); return r;
}
__device__ __forceinline__ float bf2f(uint16_t h) {
    return __uint_as_float(((uint32_t)h) << 16);
}
__device__ __forceinline__ void split2(float a0, float a1, uint32_t& hi, uint32_t& lo) {
    uint16_t h0 = f2bf(a0), h1 = f2bf(a1);
    uint16_t l0 = f2bf(a0 - bf2f(h0)), l1 = f2bf(a1 - bf2f(h1));
    hi = (uint32_t)h0 | ((uint32_t)h1 << 16);
    lo = (uint32_t)l0 | ((uint32_t)l1 << 16);
}
__device__ __forceinline__ uint32_t smem_u32(const void* p) {
    uint32_t a;
    asm("{ .reg .u64 t; cvta.to.shared.u64 t, %1; cvt.u32.u64 %0, t; }" : "=r"(a) : "l"(p));
    return a;
}

// ---------------- warp-mma primitives (baseline ISA) ----------------
__device__ __forceinline__ void ldsm4(uint32_t r[4], uint32_t a) {
    asm volatile("ldmatrix.sync.aligned.m8n8.x4.shared.b16 {%0,%1,%2,%3}, [%4];"
        : "=r"(r[0]), "=r"(r[1]), "=r"(r[2]), "=r"(r[3]) : "r"(a));
}
__device__ __forceinline__ void ldsm4t(uint32_t r[4], uint32_t a) {
    asm volatile("ldmatrix.sync.aligned.m8n8.x4.trans.shared.b16 {%0,%1,%2,%3}, [%4];"
        : "=r"(r[0]), "=r"(r[1]), "=r"(r[2]), "=r"(r[3]) : "r"(a));
}
__device__ __forceinline__ void mma16816(float* c, const uint32_t* a, uint32_t b0, uint32_t b1) {
    asm volatile("mma.sync.aligned.m16n8k16.row.col.f32.bf16.bf16.f32 "
        "{%0,%1,%2,%3}, {%4,%5,%6,%7}, {%8,%9}, {%0,%1,%2,%3};"
        : "+f"(c[0]), "+f"(c[1]), "+f"(c[2]), "+f"(c[3])
        : "r"(a[0]), "r"(a[1]), "r"(a[2]), "r"(a[3]), "r"(b0), "r"(b1));
}

// smem tile geometry: [64 rows][40 bf16] = 80B rows; chunks 0..3 (16B),
// stored at chunk' = chunk ^ ((row>>3)&3) -> conflict-free STS + LDSM.
#define MAT_STRIDE 10240
#define LO_OFF 5120
#define SMEM_TOTAL 30720

__device__ __forceinline__ uint32_t faddr(uint32_t base, int rowbase, int c0, int lane) {
    int row = rowbase + (lane & 15);
    int chunk = (c0 + (lane >> 4)) ^ ((row >> 3) & 3);
    return base + row * 80 + chunk * 16;
}

// ---------------------------------------------------------------------------
// Kernel 1: relative-position bias MLP -> g_bias[h][n][m]
// ---------------------------------------------------------------------------
__global__ __launch_bounds__(256)
void bias_kernel(const float* __restrict__ rel_pos,
                 const float* __restrict__ w1,
                 const float* __restrict__ b1,
                 const float* __restrict__ w2,
                 const float* __restrict__ b2) {
    __shared__ float w1a[256], w1b[256], b1s[256];
    __shared__ float4 w2s[512];
    const int t = threadIdx.x;
    w1a[t] = w1[t];
    w1b[t] = w1[256 + t];
    b1s[t] = b1[t];
#pragma unroll
    for (int i = t; i < 512; i += 256)
        w2s[i] = ((const float4*)w2)[i];
    __syncthreads();

    const int nm = blockIdx.x * 256 + t;
    const float r0 = rel_pos[2 * nm];
    const float r1 = rel_pos[2 * nm + 1];
    ull acc[4] = {0ull, 0ull, 0ull, 0ull};
    const ulonglong2* w2u = (const ulonglong2*)w2s;
#pragma unroll 8
    for (int k = 0; k < 256; k++) {
        float hk = fmaxf(fmaf(r0, w1a[k], fmaf(r1, w1b[k], b1s[k])), 0.f);
        ull hd = dup2(hk);
        ulonglong2 wa = w2u[2 * k];
        ulonglong2 wb = w2u[2 * k + 1];
        acc[0] = ffma2(hd, wa.x, acc[0]);
        acc[1] = ffma2(hd, wa.y, acc[1]);
        acc[2] = ffma2(hd, wb.x, acc[2]);
        acc[3] = ffma2(hd, wb.y, acc[3]);
    }
#pragma unroll
    for (int p = 0; p < 4; p++) {
        float2 v = u2f2(acc[p]);
        g_bias[(2 * p) * (NTOK * NTOK) + nm] = v.x + b2[2 * p];
        g_bias[(2 * p + 1) * (NTOK * NTOK) + nm] = v.y + b2[2 * p + 1];
    }
}

// ---------------------------------------------------------------------------
// Kernel 2: warp-mma attention. CTA=(b,h,branch), 4 warps = 4 m-quarters.
// bf16 hi/lo split (3 products) on HMMA; bias from L2; scale folded into
// the softmax bias-FMA. 5 CTAs/SM via reg ceiling.
// ---------------------------------------------------------------------------
__global__ __launch_bounds__(128, 5)
void attn_kernel(const float* __restrict__ qkv,
                 const float* __restrict__ ass_qkv,
                 float* __restrict__ out, int B) {
    extern __shared__ char sm[];
    const int b = blockIdx.y;
    const int h = blockIdx.x >> 1;
    const int branch = blockIdx.x & 1;
    const int t = threadIdx.x;
    const int lane = t & 31, w = t >> 5;
    const float scale = 0.17677669529663687f;

    // ---- cooperative gmem -> smem (split bf16 hi/lo, swizzled) ----
    {
        const float* srcb = (branch ? ass_qkv : qkv) + (size_t)b * (NTOK * 3 * DIM) + h * HD;
        const int f = t & 7;
        const int tokbase = t >> 3;          // 0..15
#pragma unroll
        for (int it = 0; it < 12; it++) {
            const int mat = it >> 2;
            const int tok = (it & 3) * 16 + tokbase;
            const float4 v = *(const float4*)(srcb + tok * (3 * DIM) + mat * DIM + f * 4);
            uint32_t h01, l01, h23, l23;
            split2(v.x, v.y, h01, l01);
            split2(v.z, v.w, h23, l23);
            char* base = sm + mat * MAT_STRIDE;
            const int off = tok * 80 + 16 * ((f >> 1) ^ ((tok >> 3) & 3)) + 8 * (f & 1);
            *(uint2*)(base + off) = make_uint2(h01, h23);
            *(uint2*)(base + LO_OFF + off) = make_uint2(l01, l23);
        }
    }
    __syncthreads();

    const int mb = w * 16;           // m-quarter base row
    const uint32_t sbase = smem_u32(sm);
    const uint32_t qh = sbase, ql = sbase + LO_OFF;
    const uint32_t kh = sbase + MAT_STRIDE, kl = kh + LO_OFF;
    const uint32_t vh = sbase + 2 * MAT_STRIDE, vl = vh + LO_OFF;

    // ---- S = q @ k^T : 1 m16-tile x 8 n8-tiles, 3 split products ----
    float sacc[8][4];
#pragma unroll
    for (int nt = 0; nt < 8; nt++)
#pragma unroll
        for (int c = 0; c < 4; c++) sacc[nt][c] = 0.f;

#pragma unroll
    for (int ks = 0; ks < 2; ks++) {
        uint32_t a_h[4], a_l[4];
        ldsm4(a_h, faddr(qh, mb, 2 * ks, lane));
        ldsm4(a_l, faddr(ql, mb, 2 * ks, lane));
#pragma unroll
        for (int g = 0; g < 4; g++) {
            uint32_t bh[4], bl[4];
            ldsm4(bh, faddr(kh, 16 * g, 2 * ks, lane));
            ldsm4(bl, faddr(kl, 16 * g, 2 * ks, lane));
            mma16816(sacc[2 * g], a_h, bh[0], bh[2]);
            mma16816(sacc[2 * g + 1], a_h, bh[1], bh[3]);
            mma16816(sacc[2 * g], a_h, bl[0], bl[2]);
            mma16816(sacc[2 * g + 1], a_h, bl[1], bl[3]);
            mma16816(sacc[2 * g], a_l, bh[0], bh[2]);
            mma16816(sacc[2 * g + 1], a_l, bh[1], bh[3]);
        }
    }

    // ---- bias (L2) + scale fold + softmax in registers ----
    const int r0 = lane >> 2, c2 = (lane & 3) * 2;
    float inva, invb;
    {
        const int rowA = mb + r0;
        const float* bp = g_bias + h * (NTOK * NTOK);
        float mxa = -1e30f, mxb = -1e30f;
#pragma unroll
        for (int nt = 0; nt < 8; nt++) {
            float2 ba = __ldg((const float2*)(bp + rowA * NTOK + nt * 8 + c2));
            float2 bbv = __ldg((const float2*)(bp + (rowA + 8) * NTOK + nt * 8 + c2));
            sacc[nt][0] = fmaf(sacc[nt][0], scale, ba.x);
            sacc[nt][1] = fmaf(sacc[nt][1], scale, ba.y);
            sacc[nt][2] = fmaf(sacc[nt][2], scale, bbv.x);
            sacc[nt][3] = fmaf(sacc[nt][3], scale, bbv.y);
            mxa = fmaxf(mxa, fmaxf(sacc[nt][0], sacc[nt][1]));
            mxb = fmaxf(mxb, fmaxf(sacc[nt][2], sacc[nt][3]));
        }
        mxa = fmaxf(mxa, __shfl_xor_sync(0xffffffffu, mxa, 1));
        mxa = fmaxf(mxa, __shfl_xor_sync(0xffffffffu, mxa, 2));
        mxb = fmaxf(mxb, __shfl_xor_sync(0xffffffffu, mxb, 1));
        mxb = fmaxf(mxb, __shfl_xor_sync(0xffffffffu, mxb, 2));
        float sa = 0.f, sb = 0.f;
#pragma unroll
        for (int nt = 0; nt < 8; nt++) {
            sacc[nt][0] = __expf(sacc[nt][0] - mxa);
            sacc[nt][1] = __expf(sacc[nt][1] - mxa);
            sacc[nt][2] = __expf(sacc[nt][2] - mxb);
            sacc[nt][3] = __expf(sacc[nt][3] - mxb);
            sa += sacc[nt][0] + sacc[nt][1];
            sb += sacc[nt][2] + sacc[nt][3];
        }
        sa += __shfl_xor_sync(0xffffffffu, sa, 1);
        sa += __shfl_xor_sync(0xffffffffu, sa, 2);
        sb += __shfl_xor_sync(0xffffffffu, sb, 1);
        sb += __shfl_xor_sync(0xffffffffu, sb, 2);
        inva = __fdividef(1.0f, sa);
        invb = __fdividef(1.0f, sb);
    }

    // ---- O = P @ V : P fragments from registers, V via ldsm.trans ----
    float oacc[4][4];
#pragma unroll
    for (int dt = 0; dt < 4; dt++)
#pragma unroll
        for (int c = 0; c < 4; c++) oacc[dt][c] = 0.f;

#pragma unroll
    for (int kk = 0; kk < 4; kk++) {
        uint32_t ph[4], pl[4];
        split2(sacc[2 * kk][0], sacc[2 * kk][1], ph[0], pl[0]);
        split2(sacc[2 * kk][2], sacc[2 * kk][3], ph[1], pl[1]);
        split2(sacc[2 * kk + 1][0], sacc[2 * kk + 1][1], ph[2], pl[2]);
        split2(sacc[2 * kk + 1][2], sacc[2 * kk + 1][3], ph[3], pl[3]);
#pragma unroll
        for (int dg = 0; dg < 2; dg++) {
            uint32_t vh4[4], vl4[4];
            ldsm4t(vh4, faddr(vh, 16 * kk, 2 * dg, lane));
            ldsm4t(vl4, faddr(vl, 16 * kk, 2 * dg, lane));
            mma16816(oacc[2 * dg], ph, vh4[0], vh4[1]);
            mma16816(oacc[2 * dg + 1], ph, vh4[2], vh4[3]);
            mma16816(oacc[2 * dg], ph, vl4[0], vl4[1]);
            mma16816(oacc[2 * dg + 1], ph, vl4[2], vl4[3]);
            mma16816(oacc[2 * dg], pl, vh4[0], vh4[1]);
            mma16816(oacc[2 * dg + 1], pl, vh4[2], vh4[3]);
        }
    }

    // ---- normalize + store ----
    float* ob = out + (size_t)branch * B * NTOK * DIM + (size_t)b * NTOK * DIM + h * HD;
    const int rowA = mb + r0;
#pragma unroll
    for (int dt = 0; dt < 4; dt++) {
        const int d = dt * 8 + c2;
        *(float2*)(ob + rowA * DIM + d) =
            make_float2(oacc[dt][0] * inva, oacc[dt][1] * inva);
        *(float2*)(ob + (rowA + 8) * DIM + d) =
            make_float2(oacc[dt][2] * invb, oacc[dt][3] * invb);
    }
}

// ---------------------------------------------------------------------------
extern "C" void kernel_launch(void* const* d_in, const int* in_sizes, int n_in,
                              void* d_out, int out_size) {
    const float* qkv     = (const float*)d_in[0];
    const float* ass_qkv = (const float*)d_in[1];
    const float* rel_pos = (const float*)d_in[2];
    const float* w1      = (const float*)d_in[3];
    const float* b1      = (const float*)d_in[4];
    const float* w2      = (const float*)d_in[5];
    const float* b2      = (const float*)d_in[6];
    float* out = (float*)d_out;

    const int B = in_sizes[0] / (NTOK * 3 * DIM);  // 2048

    cudaFuncSetAttribute(attn_kernel, cudaFuncAttributeMaxDynamicSharedMemorySize, SMEM_TOTAL);

    bias_kernel<<<16, 256>>>(rel_pos, w1, b1, w2, b2);
    attn_kernel<<<dim3(HEADS * 2, B), 128, SMEM_TOTAL>>>(qkv, ass_qkv, out, B);
}